// round 3
// baseline (speedup 1.0000x reference)
#include <cuda_runtime.h>
#include <cstdint>

// Problem dims
#define N_NODES 8192
#define DIMD    128
#define UNITS   128
#define RELS    4

// Main GEMM: out[n][u] = sum_{r,m} adj[r][n][m] * Yt[r][u][m],  K = 32768
#define MTILE   64          // rows per CTA  -> 128 CTAs
#define KT      32          // k-chunk staged through smem
#define KTOTAL  (RELS * N_NODES)
#define NCHUNK  (KTOTAL / KT)   // 1024

// Scratch (device global — no allocation allowed)
__device__ float g_Yt[(size_t)RELS * UNITS * N_NODES];   // [r][u][m], 16 MB

__device__ __forceinline__ uint32_t to_tf32_rna(float x) {
    uint32_t u;
    asm("cvt.rna.tf32.f32 %0, %1;" : "=r"(u) : "f"(x));
    return u;
}

__device__ __forceinline__ void mma_tf32(float* c, const uint32_t* a, const uint32_t* b) {
    asm volatile(
        "mma.sync.aligned.m16n8k8.row.col.f32.tf32.tf32.f32 "
        "{%0,%1,%2,%3}, {%4,%5,%6,%7}, {%8,%9}, {%0,%1,%2,%3};"
        : "+f"(c[0]), "+f"(c[1]), "+f"(c[2]), "+f"(c[3])
        : "r"(a[0]), "r"(a[1]), "r"(a[2]), "r"(a[3]), "r"(b[0]), "r"(b[1]));
}

// -------------------------------------------- kernel 1: Yt[r][u][m] = (X @ W[r])^T
// Register-blocked 8x8 SGEMM in fp32; results rounded to tf32 (rna) so the main
// GEMM's B operand carries no additional rounding.
__global__ __launch_bounds__(256) void yt_kernel(const float* __restrict__ X,
                                                 const float* __restrict__ W) {
    __shared__ float Xs[16][128];   // [d][m] (transposed on load)
    __shared__ float Ws[16][128];   // [d][u]
    const int tid = threadIdx.x;
    const int mbase = blockIdx.x * 128;
    const int r = blockIdx.y;
    const int tx = tid & 15, ty = tid >> 4;
    const int m0 = tx * 8, u0 = ty * 8;

    float acc[8][8];
    #pragma unroll
    for (int j = 0; j < 8; j++)
        #pragma unroll
        for (int i = 0; i < 8; i++) acc[j][i] = 0.f;

    const int mrow = tid >> 1, half = tid & 1;
    for (int d0 = 0; d0 < 128; d0 += 16) {
        __syncthreads();
        const float* xs = X + (size_t)(mbase + mrow) * 128 + d0 + half * 8;
        float4 a0 = *(const float4*)xs;
        float4 a1 = *(const float4*)(xs + 4);
        Xs[half*8+0][mrow] = a0.x; Xs[half*8+1][mrow] = a0.y;
        Xs[half*8+2][mrow] = a0.z; Xs[half*8+3][mrow] = a0.w;
        Xs[half*8+4][mrow] = a1.x; Xs[half*8+5][mrow] = a1.y;
        Xs[half*8+6][mrow] = a1.z; Xs[half*8+7][mrow] = a1.w;
        const float* ws = W + (size_t)r * 128 * 128 + (size_t)(d0 + ty) * 128 + tx * 8;
        *(float4*)&Ws[ty][tx * 8]     = *(const float4*)ws;
        *(float4*)&Ws[ty][tx * 8 + 4] = *(const float4*)(ws + 4);
        __syncthreads();

        #pragma unroll
        for (int dd = 0; dd < 16; dd++) {
            float4 xa0 = *(const float4*)&Xs[dd][m0];
            float4 xa1 = *(const float4*)&Xs[dd][m0 + 4];
            float4 wb0 = *(const float4*)&Ws[dd][u0];
            float4 wb1 = *(const float4*)&Ws[dd][u0 + 4];
            float a[8] = {xa0.x, xa0.y, xa0.z, xa0.w, xa1.x, xa1.y, xa1.z, xa1.w};
            float b[8] = {wb0.x, wb0.y, wb0.z, wb0.w, wb1.x, wb1.y, wb1.z, wb1.w};
            #pragma unroll
            for (int j = 0; j < 8; j++)
                #pragma unroll
                for (int i = 0; i < 8; i++) acc[j][i] += b[j] * a[i];
        }
    }

    #pragma unroll
    for (int j = 0; j < 8; j++) {
        uint32_t v[8];
        #pragma unroll
        for (int i = 0; i < 8; i++) v[i] = to_tf32_rna(acc[j][i]);
        float* dst = g_Yt + (size_t)(r * 128 + u0 + j) * N_NODES + mbase + m0;
        *(uint4*)dst       = *(uint4*)&v[0];
        *(uint4*)(dst + 4) = *(uint4*)&v[4];
    }
}

// -------------------------------------------- kernel 2: main GEMM via mma.sync tf32
// CTA: 64(m) x 128(u) output tile, K = 32768 in 1024 chunks of 32.
// 8 warps in 2(m) x 4(n) layout; warp tile 32x32 = 2x4 m16n8k8 fragments.
// Fused bias + relu epilogue. All loops statically bounded — cannot hang.
__global__ __launch_bounds__(256) void rgcn_mma(const float* __restrict__ adj,
                                                const float* __restrict__ bias,
                                                float* __restrict__ out) {
    __shared__ float As[64][36];    // [m][k], pad 36 -> conflict-free frag loads
    __shared__ float Bs[128][36];   // [u][k]

    const int tid = threadIdx.x;
    const int wid = tid >> 5, lane = tid & 31;
    const int warp_m = wid >> 2, warp_n = wid & 3;
    const int g = lane >> 2, q = lane & 3;
    const int mtile = blockIdx.x;

    // global->smem staging roles
    const int arow = tid >> 2, aseg = tid & 3;     // A: 64 rows x 4 segs of 8 floats
    const int brow = tid >> 1, bhalf = tid & 1;    // B: 128 rows x 2 halves of 16 floats

    float acc[2][4][4];
    #pragma unroll
    for (int mt = 0; mt < 2; mt++)
        #pragma unroll
        for (int nt = 0; nt < 4; nt++)
            #pragma unroll
            for (int i = 0; i < 4; i++) acc[mt][nt][i] = 0.f;

    float4 stA[2];
    float4 stB[4];

    // prefetch chunk 0
    {
        const float* pa = adj + ((size_t)(mtile * MTILE + arow)) * N_NODES + aseg * 8;
        stA[0] = *(const float4*)pa;
        stA[1] = *(const float4*)(pa + 4);
        const float* pb = g_Yt + (size_t)brow * N_NODES + bhalf * 16;
        #pragma unroll
        for (int i = 0; i < 4; i++) stB[i] = *(const float4*)(pb + i * 4);
    }

    for (int c = 0; c < NCHUNK; c++) {
        // stage current chunk into smem (A converted to tf32-rna)
        {
            float av[8] = {stA[0].x, stA[0].y, stA[0].z, stA[0].w,
                           stA[1].x, stA[1].y, stA[1].z, stA[1].w};
            #pragma unroll
            for (int i = 0; i < 8; i++)
                As[arow][aseg * 8 + i] = __uint_as_float(to_tf32_rna(av[i]));
            #pragma unroll
            for (int i = 0; i < 4; i++)
                *(float4*)&Bs[brow][bhalf * 16 + i * 4] = stB[i];
        }
        __syncthreads();

        // prefetch next chunk
        if (c + 1 < NCHUNK) {
            const int kc = (c + 1) * KT;
            const int r = kc >> 13;
            const int kin = kc & (N_NODES - 1);
            const float* pa = adj + ((size_t)r * N_NODES + mtile * MTILE + arow) * N_NODES
                              + kin + aseg * 8;
            stA[0] = *(const float4*)pa;
            stA[1] = *(const float4*)(pa + 4);
            const float* pb = g_Yt + ((size_t)r * UNITS + brow) * N_NODES + kin + bhalf * 16;
            #pragma unroll
            for (int i = 0; i < 4; i++) stB[i] = *(const float4*)(pb + i * 4);
        }

        // compute: 4 k-steps of 8
        #pragma unroll
        for (int kk = 0; kk < KT; kk += 8) {
            uint32_t af[2][4];
            #pragma unroll
            for (int mt = 0; mt < 2; mt++) {
                const int mb = warp_m * 32 + mt * 16;
                af[mt][0] = __float_as_uint(As[mb + g    ][kk + q    ]);
                af[mt][1] = __float_as_uint(As[mb + g + 8][kk + q    ]);
                af[mt][2] = __float_as_uint(As[mb + g    ][kk + q + 4]);
                af[mt][3] = __float_as_uint(As[mb + g + 8][kk + q + 4]);
            }
            uint32_t bf[4][2];
            #pragma unroll
            for (int nt = 0; nt < 4; nt++) {
                const int nb = warp_n * 32 + nt * 8;
                bf[nt][0] = __float_as_uint(Bs[nb + g][kk + q    ]);
                bf[nt][1] = __float_as_uint(Bs[nb + g][kk + q + 4]);
            }
            #pragma unroll
            for (int mt = 0; mt < 2; mt++)
                #pragma unroll
                for (int nt = 0; nt < 4; nt++)
                    mma_tf32(acc[mt][nt], af[mt], bf[nt]);
        }
        __syncthreads();
    }

    // epilogue: bias + relu, direct to out
    #pragma unroll
    for (int mt = 0; mt < 2; mt++) {
        #pragma unroll
        for (int nt = 0; nt < 4; nt++) {
            const int row0 = mtile * MTILE + warp_m * 32 + mt * 16 + g;
            const int col  = warp_n * 32 + nt * 8 + 2 * q;
            const float b0 = bias[col], b1 = bias[col + 1];
            float2 v0, v1;
            v0.x = fmaxf(acc[mt][nt][0] + b0, 0.f);
            v0.y = fmaxf(acc[mt][nt][1] + b1, 0.f);
            v1.x = fmaxf(acc[mt][nt][2] + b0, 0.f);
            v1.y = fmaxf(acc[mt][nt][3] + b1, 0.f);
            *(float2*)(out + (size_t)row0 * UNITS + col)       = v0;
            *(float2*)(out + (size_t)(row0 + 8) * UNITS + col) = v1;
        }
    }
}

// -------------------------------------------- host
extern "C" void kernel_launch(void* const* d_in, const int* in_sizes, int n_in,
                              void* d_out, int out_size) {
    // Resolve inputs by element count (robust to ordering), positional fallback.
    const float *X = nullptr, *adj = nullptr, *W = nullptr, *bias = nullptr;
    for (int i = 0; i < n_in; i++) {
        const long long sz = in_sizes[i];
        if (sz == (long long)RELS * N_NODES * N_NODES) adj  = (const float*)d_in[i];
        else if (sz == (long long)N_NODES * DIMD)      X    = (const float*)d_in[i];
        else if (sz == (long long)RELS * DIMD * UNITS) W    = (const float*)d_in[i];
        else if (sz == UNITS)                          bias = (const float*)d_in[i];
    }
    if (!X)    X    = (const float*)d_in[0];
    if (!adj)  adj  = (const float*)d_in[1];
    if (!W)    W    = (const float*)d_in[2];
    if (!bias) bias = (const float*)d_in[3];

    yt_kernel<<<dim3(N_NODES / 128, RELS), 256>>>(X, W);
    rgcn_mma<<<N_NODES / MTILE, 256>>>(adj, bias, (float*)d_out);
}

// round 5
// speedup vs baseline: 2.7963x; 2.7963x over previous
#include <cuda_runtime.h>
#include <cstdint>

// Problem dims
#define N_NODES 8192
#define DIMD    128
#define UNITS   128
#define RELS    4

// Main GEMM: part[r][n][u] = sum_m adj[r][n][m] * Yt[r][u][m]
// Split K by relation: each CTA handles exactly one r (K-range 8192).
#define MTILE   128
#define KT      32
#define NCHUNK  (N_NODES / KT)      // 256 chunks per CTA
#define STAGES  3
#define APAD    36                  // 36-float row pitch: conflict-free frags

// Scratch (device globals — no allocation allowed)
__device__ float g_Yt[(size_t)RELS * UNITS * N_NODES];    // [r][u][m], 16 MB
__device__ float g_part[(size_t)RELS * N_NODES * UNITS];  // per-relation partials, 16 MB

__device__ __forceinline__ uint32_t smem_u32(const void* p) {
    uint32_t a;
    asm("{ .reg .u64 t; cvta.to.shared.u64 t, %1; cvt.u32.u64 %0, t; }" : "=r"(a) : "l"(p));
    return a;
}
__device__ __forceinline__ uint32_t to_tf32_rna(float x) {
    uint32_t u;
    asm("cvt.rna.tf32.f32 %0, %1;" : "=r"(u) : "f"(x));
    return u;
}
__device__ __forceinline__ void cpasync16(uint32_t dst, const void* src) {
    asm volatile("cp.async.cg.shared.global [%0], [%1], 16;" :: "r"(dst), "l"(src) : "memory");
}
__device__ __forceinline__ void cp_commit() {
    asm volatile("cp.async.commit_group;" ::: "memory");
}
template <int N>
__device__ __forceinline__ void cp_wait() {
    asm volatile("cp.async.wait_group %0;" :: "n"(N) : "memory");
}
__device__ __forceinline__ void mma_tf32(float* c, const uint32_t* a, const uint32_t* b) {
    asm volatile(
        "mma.sync.aligned.m16n8k8.row.col.f32.tf32.tf32.f32 "
        "{%0,%1,%2,%3}, {%4,%5,%6,%7}, {%8,%9}, {%0,%1,%2,%3};"
        : "+f"(c[0]), "+f"(c[1]), "+f"(c[2]), "+f"(c[3])
        : "r"(a[0]), "r"(a[1]), "r"(a[2]), "r"(a[3]), "r"(b[0]), "r"(b[1]));
}

// -------------------------------------------- kernel 1: Yt[r][u][m] = (X @ W[r])^T
// fp32 SGEMM; results scaled by (1 + ln2*2^-11) to cancel the HW tf32-truncation
// bias on the raw-fp32 adj operand, then rna-rounded to tf32.
__global__ __launch_bounds__(256) void yt_kernel(const float* __restrict__ X,
                                                 const float* __restrict__ W) {
    __shared__ float Xs[16][128];
    __shared__ float Ws[16][128];
    const int tid = threadIdx.x;
    const int mbase = blockIdx.x * 128;
    const int r = blockIdx.y;
    const int tx = tid & 15, ty = tid >> 4;
    const int m0 = tx * 8, u0 = ty * 8;

    float acc[8][8];
    #pragma unroll
    for (int j = 0; j < 8; j++)
        #pragma unroll
        for (int i = 0; i < 8; i++) acc[j][i] = 0.f;

    const int mrow = tid >> 1, half = tid & 1;
    for (int d0 = 0; d0 < 128; d0 += 16) {
        __syncthreads();
        const float* xs = X + (size_t)(mbase + mrow) * 128 + d0 + half * 8;
        float4 a0 = *(const float4*)xs;
        float4 a1 = *(const float4*)(xs + 4);
        Xs[half*8+0][mrow] = a0.x; Xs[half*8+1][mrow] = a0.y;
        Xs[half*8+2][mrow] = a0.z; Xs[half*8+3][mrow] = a0.w;
        Xs[half*8+4][mrow] = a1.x; Xs[half*8+5][mrow] = a1.y;
        Xs[half*8+6][mrow] = a1.z; Xs[half*8+7][mrow] = a1.w;
        const float* ws = W + (size_t)r * 128 * 128 + (size_t)(d0 + ty) * 128 + tx * 8;
        *(float4*)&Ws[ty][tx * 8]     = *(const float4*)ws;
        *(float4*)&Ws[ty][tx * 8 + 4] = *(const float4*)(ws + 4);
        __syncthreads();

        #pragma unroll
        for (int dd = 0; dd < 16; dd++) {
            float4 xa0 = *(const float4*)&Xs[dd][m0];
            float4 xa1 = *(const float4*)&Xs[dd][m0 + 4];
            float4 wb0 = *(const float4*)&Ws[dd][u0];
            float4 wb1 = *(const float4*)&Ws[dd][u0 + 4];
            float a[8] = {xa0.x, xa0.y, xa0.z, xa0.w, xa1.x, xa1.y, xa1.z, xa1.w};
            float b[8] = {wb0.x, wb0.y, wb0.z, wb0.w, wb1.x, wb1.y, wb1.z, wb1.w};
            #pragma unroll
            for (int j = 0; j < 8; j++)
                #pragma unroll
                for (int i = 0; i < 8; i++) acc[j][i] += b[j] * a[i];
        }
    }

    const float COMP = 1.000339f;   // 1 + ln2*2^-11
    #pragma unroll
    for (int j = 0; j < 8; j++) {
        uint32_t v[8];
        #pragma unroll
        for (int i = 0; i < 8; i++) v[i] = to_tf32_rna(acc[j][i] * COMP);
        float* dst = g_Yt + (size_t)(r * 128 + u0 + j) * N_NODES + mbase + m0;
        *(uint4*)dst       = *(uint4*)&v[0];
        *(uint4*)(dst + 4) = *(uint4*)&v[4];
    }
}

// -------------------------------------------- kernel 2: main GEMM (mma.sync tf32)
// CTA: 128(m) x 128(u), K = 8192 (one relation). 256 CTAs, 2 CTAs/SM.
// cp.async 3-stage ring, ONE __syncthreads per chunk.
// 8 warps in 2(m) x 4(n); warp tile 64x32 = 4x4 m16n8k8 fragments.
__global__ __launch_bounds__(256, 2) void rgcn_mma(const float* __restrict__ adj) {
    extern __shared__ float smem[];
    // stage s: A at s*2*MTILE*APAD, B at that + MTILE*APAD   (36864 B per stage)
    float* As = smem;                          // [STAGES][128][APAD]
    float* Bs = smem + MTILE * APAD;           // interleaved per stage

    const int tid = threadIdx.x;
    const int wid = tid >> 5, lane = tid & 31;
    const int warp_m = wid >> 2, warp_n = wid & 3;
    const int g = lane >> 2, q = lane & 3;
    const int mtile = blockIdx.x >> 2;
    const int r = blockIdx.x & 3;

    const float* gA = adj + ((size_t)r * N_NODES + (size_t)mtile * MTILE) * N_NODES;
    const float* gB = g_Yt + (size_t)r * UNITS * N_NODES;
    const uint32_t sbase = smem_u32(smem);

    // staging: A tile 128x32 (8 segs of 16B per row) = 1024 ops; B same. 4+4 ops/thread.
    const int srow = tid >> 3, sseg = tid & 7;   // + j*32 rows

    auto stage_chunk = [&](int c) {
        const int kin = c * KT;
        const uint32_t sa = sbase + (uint32_t)(c % STAGES) * (2u * MTILE * APAD * 4u);
        const uint32_t sb = sa + MTILE * APAD * 4u;
        #pragma unroll
        for (int j = 0; j < 4; j++) {
            const int row = srow + j * 32;
            const uint32_t soff = (uint32_t)(row * APAD + sseg * 4) * 4u;
            cpasync16(sa + soff, gA + (size_t)row * N_NODES + kin + sseg * 4);
            cpasync16(sb + soff, gB + (size_t)row * N_NODES + kin + sseg * 4);
        }
        cp_commit();
    };

    float acc[4][4][4];
    #pragma unroll
    for (int mt = 0; mt < 4; mt++)
        #pragma unroll
        for (int nt = 0; nt < 4; nt++)
            #pragma unroll
            for (int i = 0; i < 4; i++) acc[mt][nt][i] = 0.f;

    stage_chunk(0);
    stage_chunk(1);

    for (int c = 0; c < NCHUNK; c++) {
        if (c + 1 < NCHUNK) cp_wait<1>(); else cp_wait<0>();
        __syncthreads();                 // chunk c visible to all; slot (c+2)%3 free
        if (c + 2 < NCHUNK) stage_chunk(c + 2);

        const float* a_s = smem + (size_t)(c % STAGES) * (2 * MTILE * APAD);
        const float* b_s = a_s + MTILE * APAD;

        #pragma unroll
        for (int k8 = 0; k8 < KT; k8 += 8) {
            uint32_t af[4][4];
            #pragma unroll
            for (int mt = 0; mt < 4; mt++) {
                const int mb = warp_m * 64 + mt * 16;
                af[mt][0] = __float_as_uint(a_s[(mb + g    ) * APAD + k8 + q    ]);
                af[mt][1] = __float_as_uint(a_s[(mb + g + 8) * APAD + k8 + q    ]);
                af[mt][2] = __float_as_uint(a_s[(mb + g    ) * APAD + k8 + q + 4]);
                af[mt][3] = __float_as_uint(a_s[(mb + g + 8) * APAD + k8 + q + 4]);
            }
            uint32_t bf[4][2];
            #pragma unroll
            for (int nt = 0; nt < 4; nt++) {
                const int nb = warp_n * 32 + nt * 8;
                bf[nt][0] = __float_as_uint(b_s[(nb + g) * APAD + k8 + q    ]);
                bf[nt][1] = __float_as_uint(b_s[(nb + g) * APAD + k8 + q + 4]);
            }
            #pragma unroll
            for (int mt = 0; mt < 4; mt++)
                #pragma unroll
                for (int nt = 0; nt < 4; nt++)
                    mma_tf32(acc[mt][nt], af[mt], bf[nt]);
        }
        __syncthreads();                 // all warps done with slot c before restage
    }

    // epilogue -> per-relation partials
    float* base = g_part + (size_t)r * N_NODES * UNITS;
    #pragma unroll
    for (int mt = 0; mt < 4; mt++) {
        #pragma unroll
        for (int nt = 0; nt < 4; nt++) {
            const int row0 = mtile * MTILE + warp_m * 64 + mt * 16 + g;
            const int col  = warp_n * 32 + nt * 8 + 2 * q;
            *(float2*)(base + (size_t)row0 * UNITS + col) =
                make_float2(acc[mt][nt][0], acc[mt][nt][1]);
            *(float2*)(base + (size_t)(row0 + 8) * UNITS + col) =
                make_float2(acc[mt][nt][2], acc[mt][nt][3]);
        }
    }
}

// -------------------------------------------- kernel 3: sum 4 partials + bias + relu
__global__ __launch_bounds__(256) void reduce_kernel(const float* __restrict__ bias,
                                                     float* __restrict__ out) {
    const int i = blockIdx.x * 256 + threadIdx.x;   // float4 index
    const size_t stride = (size_t)N_NODES * UNITS / 4;
    const float4* p = (const float4*)g_part;
    float4 a0 = p[i], a1 = p[i + stride], a2 = p[i + 2 * stride], a3 = p[i + 3 * stride];
    float4 bb = *(const float4*)(bias + ((i * 4) & (UNITS - 1)));
    float4 o;
    o.x = fmaxf(a0.x + a1.x + a2.x + a3.x + bb.x, 0.f);
    o.y = fmaxf(a0.y + a1.y + a2.y + a3.y + bb.y, 0.f);
    o.z = fmaxf(a0.z + a1.z + a2.z + a3.z + bb.z, 0.f);
    o.w = fmaxf(a0.w + a1.w + a2.w + a3.w + bb.w, 0.f);
    ((float4*)out)[i] = o;
}

#define MAIN_SMEM (STAGES * 2 * MTILE * APAD * 4)   // 110592 B

// -------------------------------------------- host
extern "C" void kernel_launch(void* const* d_in, const int* in_sizes, int n_in,
                              void* d_out, int out_size) {
    const float *X = nullptr, *adj = nullptr, *W = nullptr, *bias = nullptr;
    for (int i = 0; i < n_in; i++) {
        const long long sz = in_sizes[i];
        if (sz == (long long)RELS * N_NODES * N_NODES) adj  = (const float*)d_in[i];
        else if (sz == (long long)N_NODES * DIMD)      X    = (const float*)d_in[i];
        else if (sz == (long long)RELS * DIMD * UNITS) W    = (const float*)d_in[i];
        else if (sz == UNITS)                          bias = (const float*)d_in[i];
    }
    if (!X)    X    = (const float*)d_in[0];
    if (!adj)  adj  = (const float*)d_in[1];
    if (!W)    W    = (const float*)d_in[2];
    if (!bias) bias = (const float*)d_in[3];

    cudaFuncSetAttribute(rgcn_mma, cudaFuncAttributeMaxDynamicSharedMemorySize, MAIN_SMEM);

    yt_kernel<<<dim3(N_NODES / 128, RELS), 256>>>(X, W);
    rgcn_mma<<<(N_NODES / MTILE) * RELS, 256, MAIN_SMEM>>>(adj);
    reduce_kernel<<<(N_NODES * UNITS) / 4 / 256, 256>>>(bias, (float*)d_out);
}

// round 7
// speedup vs baseline: 3.1526x; 1.1274x over previous
#include <cuda_runtime.h>
#include <cstdint>

// Problem dims
#define N_NODES 8192
#define DIMD    128
#define UNITS   128
#define RELS    4

// Main GEMM: part[r][n][u] = sum_m adj[r][n][m] * Yt[r][u][m]
// Split K by relation: each CTA handles one r (K = 8192).
#define MTILE   256
#define KT      32
#define NCHUNK  (N_NODES / KT)      // 256 chunks per CTA
#define STAGES  3
#define APAD    40                  // conflict-free for float2 frags + 16B stores

#define A_STG_FLOATS (MTILE * APAD)          // 10240
#define B_STG_FLOATS (UNITS * APAD)          // 5120
#define STG_FLOATS   (A_STG_FLOATS + B_STG_FLOATS)
#define MAIN_SMEM    (STAGES * STG_FLOATS * 4)   // 184320 B  (< 227KB cap)

// Scratch (device globals — no allocation allowed)
__device__ float g_Yt[(size_t)RELS * UNITS * N_NODES];    // [r][u][m], 16 MB
__device__ float g_part[(size_t)RELS * N_NODES * UNITS];  // per-relation partials, 16 MB

__device__ __forceinline__ uint32_t smem_u32(const void* p) {
    uint32_t a;
    asm("{ .reg .u64 t; cvta.to.shared.u64 t, %1; cvt.u32.u64 %0, t; }" : "=r"(a) : "l"(p));
    return a;
}
__device__ __forceinline__ uint32_t to_tf32_rna(float x) {
    uint32_t u;
    asm("cvt.rna.tf32.f32 %0, %1;" : "=r"(u) : "f"(x));
    return u;
}
__device__ __forceinline__ void cpasync16(uint32_t dst, const void* src) {
    asm volatile("cp.async.cg.shared.global [%0], [%1], 16;" :: "r"(dst), "l"(src) : "memory");
}
__device__ __forceinline__ void cp_commit() {
    asm volatile("cp.async.commit_group;" ::: "memory");
}
template <int N>
__device__ __forceinline__ void cp_wait() {
    asm volatile("cp.async.wait_group %0;" :: "n"(N) : "memory");
}
__device__ __forceinline__ void mma_tf32(float* c, const uint32_t* a, const uint32_t* b) {
    asm volatile(
        "mma.sync.aligned.m16n8k8.row.col.f32.tf32.tf32.f32 "
        "{%0,%1,%2,%3}, {%4,%5,%6,%7}, {%8,%9}, {%0,%1,%2,%3};"
        : "+f"(c[0]), "+f"(c[1]), "+f"(c[2]), "+f"(c[3])
        : "r"(a[0]), "r"(a[1]), "r"(a[2]), "r"(a[3]), "r"(b[0]), "r"(b[1]));
}

// -------------------------------------------- kernel 1: Yt[r][u][m] = (X @ W[r])^T
// fp32 SGEMM; results scaled by (1 + ln2*2^-11) to cancel the HW tf32-truncation
// bias on the raw-fp32 adj operand, then rna-rounded to tf32.
__global__ __launch_bounds__(256) void yt_kernel(const float* __restrict__ X,
                                                 const float* __restrict__ W) {
    __shared__ float Xs[16][128];
    __shared__ float Ws[16][128];
    const int tid = threadIdx.x;
    const int mbase = blockIdx.x * 128;
    const int r = blockIdx.y;
    const int tx = tid & 15, ty = tid >> 4;
    const int m0 = tx * 8, u0 = ty * 8;

    float acc[8][8];
    #pragma unroll
    for (int j = 0; j < 8; j++)
        #pragma unroll
        for (int i = 0; i < 8; i++) acc[j][i] = 0.f;

    const int mrow = tid >> 1, half = tid & 1;
    for (int d0 = 0; d0 < 128; d0 += 16) {
        __syncthreads();
        const float* xs = X + (size_t)(mbase + mrow) * 128 + d0 + half * 8;
        float4 a0 = *(const float4*)xs;
        float4 a1 = *(const float4*)(xs + 4);
        Xs[half*8+0][mrow] = a0.x; Xs[half*8+1][mrow] = a0.y;
        Xs[half*8+2][mrow] = a0.z; Xs[half*8+3][mrow] = a0.w;
        Xs[half*8+4][mrow] = a1.x; Xs[half*8+5][mrow] = a1.y;
        Xs[half*8+6][mrow] = a1.z; Xs[half*8+7][mrow] = a1.w;
        const float* ws = W + (size_t)r * 128 * 128 + (size_t)(d0 + ty) * 128 + tx * 8;
        *(float4*)&Ws[ty][tx * 8]     = *(const float4*)ws;
        *(float4*)&Ws[ty][tx * 8 + 4] = *(const float4*)(ws + 4);
        __syncthreads();

        #pragma unroll
        for (int dd = 0; dd < 16; dd++) {
            float4 xa0 = *(const float4*)&Xs[dd][m0];
            float4 xa1 = *(const float4*)&Xs[dd][m0 + 4];
            float4 wb0 = *(const float4*)&Ws[dd][u0];
            float4 wb1 = *(const float4*)&Ws[dd][u0 + 4];
            float a[8] = {xa0.x, xa0.y, xa0.z, xa0.w, xa1.x, xa1.y, xa1.z, xa1.w};
            float b[8] = {wb0.x, wb0.y, wb0.z, wb0.w, wb1.x, wb1.y, wb1.z, wb1.w};
            #pragma unroll
            for (int j = 0; j < 8; j++)
                #pragma unroll
                for (int i = 0; i < 8; i++) acc[j][i] += b[j] * a[i];
        }
    }

    const float COMP = 1.000339f;   // 1 + ln2*2^-11
    #pragma unroll
    for (int j = 0; j < 8; j++) {
        uint32_t v[8];
        #pragma unroll
        for (int i = 0; i < 8; i++) v[i] = to_tf32_rna(acc[j][i] * COMP);
        float* dst = g_Yt + (size_t)(r * 128 + u0 + j) * N_NODES + mbase + m0;
        *(uint4*)dst       = *(uint4*)&v[0];
        *(uint4*)(dst + 4) = *(uint4*)&v[4];
    }
}

// -------------------------------------------- kernel 2: main GEMM (mma.sync tf32)
// CTA: 256(m) x 128(u), K = 8192 (one relation). Grid 128.
// 8 warps in 4(m) x 2(n); warp tile 64x64 = 4x8 m16n8k8 fragments.
// cp.async 3-stage ring, ONE __syncthreads per chunk.
// k-permuted fragments (logical (q,q+4) -> physical (2q,2q+1)) => float2 LDS.
__global__ __launch_bounds__(256, 1) void rgcn_mma(const float* __restrict__ adj) {
    extern __shared__ float smem[];

    const int tid = threadIdx.x;
    const int wid = tid >> 5, lane = tid & 31;
    const int warp_m = wid >> 1, warp_n = wid & 1;
    const int g = lane >> 2, q = lane & 3;
    const int mtile = blockIdx.x >> 2;
    const int r = blockIdx.x & 3;

    const float* gA = adj + ((size_t)r * N_NODES + (size_t)mtile * MTILE) * N_NODES;
    const float* gB = g_Yt + (size_t)r * UNITS * N_NODES;
    const uint32_t sbase = smem_u32(smem);

    const int srow = tid >> 3, sseg = tid & 7;   // staging role

    auto stage_chunk = [&](int c) {
        const int kin = c * KT;
        const uint32_t sa = sbase + (uint32_t)(c % STAGES) * (STG_FLOATS * 4u);
        const uint32_t sb = sa + A_STG_FLOATS * 4u;
        #pragma unroll
        for (int j = 0; j < 4; j++) {            // interleave A (8 rows-blocks) & B (4)
            const int rowA0 = srow + (2 * j) * 32;
            const int rowA1 = srow + (2 * j + 1) * 32;
            const int rowB  = srow + j * 32;
            cpasync16(sa + (uint32_t)(rowA0 * APAD + sseg * 4) * 4u,
                      gA + (size_t)rowA0 * N_NODES + kin + sseg * 4);
            cpasync16(sb + (uint32_t)(rowB * APAD + sseg * 4) * 4u,
                      gB + (size_t)rowB * N_NODES + kin + sseg * 4);
            cpasync16(sa + (uint32_t)(rowA1 * APAD + sseg * 4) * 4u,
                      gA + (size_t)rowA1 * N_NODES + kin + sseg * 4);
        }
        cp_commit();
    };

    float acc[4][8][4];
    #pragma unroll
    for (int mt = 0; mt < 4; mt++)
        #pragma unroll
        for (int nt = 0; nt < 8; nt++)
            #pragma unroll
            for (int i = 0; i < 4; i++) acc[mt][nt][i] = 0.f;

    stage_chunk(0);
    stage_chunk(1);

    for (int c = 0; c < NCHUNK; c++) {
        if (c + 1 < NCHUNK) cp_wait<1>(); else cp_wait<0>();
        __syncthreads();                 // chunk c visible; slot (c-1)%3 consumed
        if (c + 2 < NCHUNK) stage_chunk(c + 2);

        const float* a_s = smem + (size_t)(c % STAGES) * STG_FLOATS;
        const float* b_s = a_s + A_STG_FLOATS;

        #pragma unroll
        for (int k8 = 0; k8 < KT; k8 += 8) {
            const int kc = k8 + 2 * q;           // physical col of this thread's pair
            uint32_t af[4][4];
            #pragma unroll
            for (int mt = 0; mt < 4; mt++) {
                const int mb = warp_m * 64 + mt * 16;
                float2 lo = *(const float2*)&a_s[(mb + g    ) * APAD + kc];
                float2 hi = *(const float2*)&a_s[(mb + g + 8) * APAD + kc];
                af[mt][0] = __float_as_uint(lo.x);
                af[mt][1] = __float_as_uint(hi.x);
                af[mt][2] = __float_as_uint(lo.y);
                af[mt][3] = __float_as_uint(hi.y);
            }
            uint32_t bf[8][2];
            #pragma unroll
            for (int nt = 0; nt < 8; nt++) {
                const int nb = warp_n * 64 + nt * 8;
                float2 bv = *(const float2*)&b_s[(nb + g) * APAD + kc];
                bf[nt][0] = __float_as_uint(bv.x);
                bf[nt][1] = __float_as_uint(bv.y);
            }
            #pragma unroll
            for (int mt = 0; mt < 4; mt++)
                #pragma unroll
                for (int nt = 0; nt < 8; nt++)
                    mma_tf32(acc[mt][nt], af[mt], bf[nt]);
        }
    }

    // epilogue -> per-relation partials
    float* base = g_part + (size_t)r * N_NODES * UNITS;
    #pragma unroll
    for (int mt = 0; mt < 4; mt++) {
        #pragma unroll
        for (int nt = 0; nt < 8; nt++) {
            const int row0 = mtile * MTILE + warp_m * 64 + mt * 16 + g;
            const int col  = warp_n * 64 + nt * 8 + 2 * q;
            *(float2*)(base + (size_t)row0 * UNITS + col) =
                make_float2(acc[mt][nt][0], acc[mt][nt][1]);
            *(float2*)(base + (size_t)(row0 + 8) * UNITS + col) =
                make_float2(acc[mt][nt][2], acc[mt][nt][3]);
        }
    }
}

// -------------------------------------------- kernel 3: sum 4 partials + bias + relu
__global__ __launch_bounds__(256) void reduce_kernel(const float* __restrict__ bias,
                                                     float* __restrict__ out) {
    const int i = blockIdx.x * 256 + threadIdx.x;   // float4 index
    const size_t stride = (size_t)N_NODES * UNITS / 4;
    const float4* p = (const float4*)g_part;
    float4 a0 = p[i], a1 = p[i + stride], a2 = p[i + 2 * stride], a3 = p[i + 3 * stride];
    float4 bb = *(const float4*)(bias + ((i * 4) & (UNITS - 1)));
    float4 o;
    o.x = fmaxf(a0.x + a1.x + a2.x + a3.x + bb.x, 0.f);
    o.y = fmaxf(a0.y + a1.y + a2.y + a3.y + bb.y, 0.f);
    o.z = fmaxf(a0.z + a1.z + a2.z + a3.z + bb.z, 0.f);
    o.w = fmaxf(a0.w + a1.w + a2.w + a3.w + bb.w, 0.f);
    ((float4*)out)[i] = o;
}

// -------------------------------------------- host
extern "C" void kernel_launch(void* const* d_in, const int* in_sizes, int n_in,
                              void* d_out, int out_size) {
    const float *X = nullptr, *adj = nullptr, *W = nullptr, *bias = nullptr;
    for (int i = 0; i < n_in; i++) {
        const long long sz = in_sizes[i];
        if (sz == (long long)RELS * N_NODES * N_NODES) adj  = (const float*)d_in[i];
        else if (sz == (long long)N_NODES * DIMD)      X    = (const float*)d_in[i];
        else if (sz == (long long)RELS * DIMD * UNITS) W    = (const float*)d_in[i];
        else if (sz == UNITS)                          bias = (const float*)d_in[i];
    }
    if (!X)    X    = (const float*)d_in[0];
    if (!adj)  adj  = (const float*)d_in[1];
    if (!W)    W    = (const float*)d_in[2];
    if (!bias) bias = (const float*)d_in[3];

    cudaFuncSetAttribute(rgcn_mma, cudaFuncAttributeMaxDynamicSharedMemorySize, MAIN_SMEM);

    yt_kernel<<<dim3(N_NODES / 128, RELS), 256>>>(X, W);
    rgcn_mma<<<(N_NODES / MTILE) * RELS, 256, MAIN_SMEM>>>(adj);
    reduce_kernel<<<(N_NODES * UNITS) / 4 / 256, 256>>>(bias, (float*)d_out);
}